// round 6
// baseline (speedup 1.0000x reference)
#include <cuda_runtime.h>
#include <cuda_bf16.h>
#include <math.h>

// ---------------- problem constants ----------------
#define EMB    300
#define SEQ    100
#define KW     5
#define KN     50
#define KMAX   3
#define MLP1   75
#define LP     (SEQ - KW + 1)   // 96
#define EPAD   308              // smem E row pad: %4==0 (LDS.128)
#define CE     20               // e per staged chunk
#define CQ     (CE / 4)         // 5 e-quads per chunk
#define NCH    (EMB / CE)       // 15 chunks
#define NGSTR  524              // floats per ng block: 25*CE + 16 pad (stride%32w == 12)
#define NGSTRQ (NGSTR / 4)      // 131 float4
#define CHFLT  (10 * NGSTR)     // 5240 floats per chunk (~21 KB)
#define CHQ    (CHFLT / 4)      // 1310 float4 per chunk

// ---------------- device scratch ----------------
__device__ float g_cv[EMB];
__device__ float g_gate[KN];
__device__ float g_bias[KN];
// chunked+padded: g_w2[c*CHFLT + ng*NGSTR + (j*KW+w)*CE + ei], n=5ng+j, e=c*CE+ei
__device__ __align__(16) float g_w2[NCH * CHFLT];

// packed fp32 FMA (sm_103a)
__device__ __forceinline__ float2 ffma2(float2 a, float2 b, float2 c) {
    float2 d;
    asm("fma.rn.f32x2 %0, %1, %2, %3;"
        : "=l"(*reinterpret_cast<unsigned long long*>(&d))
        : "l"(*reinterpret_cast<unsigned long long*>(&a)),
          "l"(*reinterpret_cast<unsigned long long*>(&b)),
          "l"(*reinterpret_cast<unsigned long long*>(&c)));
    return d;
}

// ---------------- prepA: class vector ----------------
__global__ void dazer_prepA(const int* __restrict__ q,
                            const float* __restrict__ emb) {
    int t = threadIdx.x;
    if (t < EMB) {
        float s = 0.f;
        #pragma unroll
        for (int k = 0; k < 5; k++) s += emb[(size_t)q[k] * EMB + t];
        g_cv[t] = s * 0.2f;
    }
}

// ---------------- prepB: gate+bias (blocks 0..49) and W fold (blocks 50..149)
__global__ void dazer_prepB(const float* __restrict__ conv_w,
                            const float* __restrict__ conv_b,
                            const float* __restrict__ gate_w,
                            const float* __restrict__ gate_b) {
    __shared__ float red[256];
    __shared__ float cvs[EMB];
    const int tid = threadIdx.x;
    const int bid = blockIdx.x;

    for (int e = tid; e < EMB; e += 256) cvs[e] = g_cv[e];
    __syncthreads();

    if (bid < KN) {
        const int n = bid;
        float s = 0.f;
        for (int e = tid; e < EMB; e += 256) s += cvs[e] * gate_w[e * KN + n];
        red[tid] = s; __syncthreads();
        for (int o = 128; o; o >>= 1) { if (tid < o) red[tid] += red[tid + o]; __syncthreads(); }
        if (tid == 0) g_gate[n] = 1.f / (1.f + expf(-(red[0] + gate_b[n])));
        __syncthreads();
        float bs = 0.f;
        for (int idx = tid; idx < KW * EMB; idx += 256) {
            int w = idx / EMB, e = idx - w * EMB;
            bs += cvs[e] * conv_w[(w * (3 * EMB) + 2 * EMB + e) * KN + n];
        }
        red[tid] = bs; __syncthreads();
        for (int o = 128; o; o >>= 1) { if (tid < o) red[tid] += red[tid + o]; __syncthreads(); }
        if (tid == 0) g_bias[n] = red[0] + conv_b[n];
    } else {
        // fold Weff = W1 + cv[e]*W2 - W3 into chunked+padded layout; zero pads
        const int total = KN * KW * EMB;   // 75000
        for (int idx = (bid - KN) * 256 + tid; idx < total; idx += 100 * 256) {
            int e    = idx % EMB;
            int w    = (idx / EMB) % KW;
            int n    = idx / (EMB * KW);
            int c    = e / CE, ei = e - c * CE;
            int ng   = n / 5,  j  = n - ng * 5;
            int base = w * (3 * EMB);
            g_w2[c * CHFLT + ng * NGSTR + (j * KW + w) * CE + ei] =
                  conv_w[(base + e) * KN + n]
                + cvs[e] * conv_w[(base + EMB + e) * KN + n]
                -          conv_w[(base + 2 * EMB + e) * KN + n];
        }
        // zero the 16-float pads (copied by cp.async; keep deterministic)
        const int npads = NCH * 10 * 16;   // 2400
        for (int p = (bid - KN) * 256 + tid; p < npads; p += 100 * 256) {
            int c  = p / 160;
            int r  = p - c * 160;
            int ng = r / 16, k = r - ng * 16;
            g_w2[c * CHFLT + ng * NGSTR + 25 * CE + k] = 0.f;
        }
    }
}

// ---------------- cp.async helpers ----------------
__device__ __forceinline__ void prefetch_chunk(const float4* __restrict__ src,
                                               float* dstbuf, int tid) {
    unsigned sbase = (unsigned)__cvta_generic_to_shared(dstbuf);
    #pragma unroll
    for (int i = 0; i < 6; i++) {
        int idx = i * 256 + tid;
        if (idx < CHQ)
            asm volatile("cp.async.cg.shared.global [%0], [%1], 16;"
                         :: "r"(sbase + idx * 16), "l"(src + idx));
    }
    asm volatile("cp.async.commit_group;" ::: "memory");
}
__device__ __forceinline__ void cpasync_wait_all() {
    asm volatile("cp.async.wait_group 0;" ::: "memory");
}

// ---------------- main fused kernel: one document per CTA ----------------
// smem floats: E 30800 | W0 5240 | W1 5240 | convs 4800 | enc 152 | mlp1 76 | docids 100
#define SMEM_FLOATS (SEQ * EPAD + 2 * CHFLT + LP * KN + 152 + 76 + 100)

__global__ __launch_bounds__(256, 1)
void dazer_main(const int* __restrict__ input_d,
                const float* __restrict__ emb,
                const float* __restrict__ hid_w,
                const float* __restrict__ hid_b,
                const float* __restrict__ score_w,
                const float* __restrict__ score_b,
                float* __restrict__ out, int Btot) {
    extern __shared__ float sm[];
    float* E      = sm;                         // [100][308]
    float* W0     = E + SEQ * EPAD;
    float* W1     = W0 + CHFLT;
    float* convs  = W1 + CHFLT;                 // [96][50]
    float* enc    = convs + LP * KN;            // [152]
    float* mlp1s  = enc + 152;                  // [76]
    int*   docids = (int*)(mlp1s + 76);         // [100]

    const int tid = threadIdx.x;
    const int b   = blockIdx.x;

    const float4* __restrict__ Wsrc = (const float4*)g_w2;

    // kick off chunk-0 W copy immediately (overlaps the E gather)
    prefetch_chunk(Wsrc, W0, tid);

    if (tid < SEQ) docids[tid] = input_d[b * SEQ + tid];
    __syncthreads();

    // gather embeddings (coalesced LDG -> padded smem rows)
    for (int idx = tid; idx < SEQ * EMB; idx += 256) {
        int s = idx / EMB;
        int e = idx - s * EMB;
        E[s * EPAD + e] = emb[(size_t)docids[s] * EMB + e];
    }

    // thread tile: 4 t-rows x 5 filters; threads 240..255 recompute tile (23,9)
    int tg = tid / 10;
    int ng = tid - tg * 10;
    const bool real = (tid < 240);
    if (!real) { tg = 23; ng = 9; }
    const int t0 = tg * 4;
    const int n0 = ng * 5;

    float2 acc[4][5];
    #pragma unroll
    for (int k = 0; k < 4; k++)
        #pragma unroll
        for (int j = 0; j < 5; j++) acc[k][j] = make_float2(0.f, 0.f);

    float* Wbuf[2] = {W0, W1};
    int sel = 0;

    #pragma unroll 1
    for (int c = 0; c < NCH; c++) {
        cpasync_wait_all();
        __syncthreads();   // chunk c landed; everyone done with buffer sel^1
        if (c + 1 < NCH) prefetch_chunk(Wsrc + (c + 1) * CHQ, Wbuf[sel ^ 1], tid);

        const float4* __restrict__ Wc = (const float4*)Wbuf[sel];
        const int wbase = ng * NGSTRQ;

        #pragma unroll
        for (int eql = 0; eql < CQ; eql++) {
            const int ecol = c * CE + eql * 4;
            float4 E4[8];
            #pragma unroll
            for (int k = 0; k < 8; k++)
                E4[k] = *(const float4*)&E[(t0 + k) * EPAD + ecol];

            #pragma unroll
            for (int j = 0; j < 5; j++) {
                #pragma unroll
                for (int w = 0; w < 5; w++) {
                    float4 w4 = Wc[wbase + (j * KW + w) * CQ + eql];  // 2-wavefront LDS.128
                    float2 wlo = make_float2(w4.x, w4.y);
                    float2 whi = make_float2(w4.z, w4.w);
                    #pragma unroll
                    for (int k = 0; k < 4; k++) {
                        float2 elo = make_float2(E4[w + k].x, E4[w + k].y);
                        float2 ehi = make_float2(E4[w + k].z, E4[w + k].w);
                        acc[k][j] = ffma2(elo, wlo, acc[k][j]);
                        acc[k][j] = ffma2(ehi, whi, acc[k][j]);
                    }
                }
            }
        }
        sel ^= 1;
    }

    // gate + bias, write conv outputs to smem
    if (real) {
        #pragma unroll
        for (int j = 0; j < 5; j++) {
            int n = n0 + j;
            float gg = g_gate[n], bb = g_bias[n];
            #pragma unroll
            for (int k = 0; k < 4; k++)
                convs[(t0 + k) * KN + n] = gg * ((acc[k][j].x + acc[k][j].y) + bb);
        }
    }
    __syncthreads();

    // top-3 (kmax) per filter, original-order (strict > == jax top_k tie-break)
    if (tid < KN) {
        const int n = tid;
        float v1 = -1e30f, v2 = -1e30f, v3 = -1e30f;
        int   i1 = 0, i2 = 0, i3 = 0;
        for (int t = 0; t < LP; t++) {
            float v = convs[t * KN + n];
            if (v > v1)      { v3 = v2; i3 = i2; v2 = v1; i2 = i1; v1 = v; i1 = t; }
            else if (v > v2) { v3 = v2; i3 = i2; v2 = v;  i2 = t; }
            else if (v > v3) { v3 = v;  i3 = t; }
        }
        float va = v1, vb = v2, vc = v3; int ia = i1, ib = i2, ic = i3;
        if (ia > ib) { float tv = va; va = vb; vb = tv; int ti = ia; ia = ib; ib = ti; }
        if (ib > ic) { float tv = vb; vb = vc; vc = tv; int ti = ib; ib = ic; ic = ti; }
        if (ia > ib) { float tv = va; va = vb; vb = tv; int ti = ia; ia = ib; ib = ti; }
        enc[n * 3 + 0] = va;
        enc[n * 3 + 1] = vb;
        enc[n * 3 + 2] = vc;
    }
    __syncthreads();

    // mlp1 = tanh(enc @ hid_w + hid_b)
    if (tid < MLP1) {
        float s = hid_b[tid];
        #pragma unroll 5
        for (int i = 0; i < KN * KMAX; i++) s += enc[i] * hid_w[i * MLP1 + tid];
        float m = tanhf(s);
        mlp1s[tid] = m;
        out[(size_t)b * MLP1 + tid] = m;
    }
    __syncthreads();

    // score = tanh(mlp1 @ score_w + score_b)
    if (tid == 0) {
        float s = score_b[0];
        for (int j = 0; j < MLP1; j++) s += mlp1s[j] * score_w[j];
        out[(size_t)Btot * MLP1 + b] = tanhf(s);
    }
}

// ---------------- launch ----------------
extern "C" void kernel_launch(void* const* d_in, const int* in_sizes, int n_in,
                              void* d_out, int out_size) {
    const int*   input_q   = (const int*)  d_in[0];
    const int*   input_d   = (const int*)  d_in[1];
    const float* emb_table = (const float*)d_in[2];
    const float* conv_w    = (const float*)d_in[3];
    const float* conv_b    = (const float*)d_in[4];
    const float* gate_w    = (const float*)d_in[5];
    const float* gate_b    = (const float*)d_in[6];
    const float* hid_w     = (const float*)d_in[7];
    const float* hid_b     = (const float*)d_in[8];
    const float* score_w   = (const float*)d_in[9];
    const float* score_b   = (const float*)d_in[10];
    float* out = (float*)d_out;

    const int Btot = in_sizes[1] / SEQ;   // 2048
    const int smem_bytes = SMEM_FLOATS * (int)sizeof(float);

    cudaFuncSetAttribute(dazer_main, cudaFuncAttributeMaxDynamicSharedMemorySize, smem_bytes);

    dazer_prepA<<<1, 320>>>(input_q, emb_table);
    dazer_prepB<<<150, 256>>>(conv_w, conv_b, gate_w, gate_b);
    dazer_main<<<Btot, 256, smem_bytes>>>(input_d, emb_table, hid_w, hid_b,
                                          score_w, score_b, out, Btot);
}